// round 14
// baseline (speedup 1.0000x reference)
#include <cuda_runtime.h>
#include <math.h>

typedef unsigned long long ull;

#define NN 30
#define FF 4
#define HH 64
#define NSAMP 2048          // 32 * 64
#define TOUT 127
#define VAROFF (32*127*30*4)
#define AST 68              // activation row stride (floats), bank-staggered
#define GS  (8*AST + 4)     // 548: 8-row group stride; +4 staggers groups across banks
#define GST 36              // dense-graph row stride (floats), bank-staggered

// Scratch (allocation-free rule: __device__ globals)
__device__ float g_agg[(size_t)NSAMP * NN * HH];   // 15.7 MB
__device__ float g_mu [(size_t)NSAMP * NN * FF];   // 0.98 MB

// ---- packed f32x2 helpers (sm_103a) ---------------------------------------
#define FFMA2(acc, a, b) \
    asm("fma.rn.f32x2 %0, %1, %2, %0;" : "+l"(acc) : "l"(a), "l"(b))
#define MUL2(d, a, b) \
    asm("mul.rn.f32x2 %0, %1, %2;" : "=l"(d) : "l"(a), "l"(b))
#define PACKDUP(d, x) \
    asm("mov.b64 %0, {%1, %1};" : "=l"(d) : "r"(__float_as_uint(x)))
#define UNPACK2(x, y, p) \
    asm("mov.b64 {%0, %1}, %2;" : "=f"(x), "=f"(y) : "l"(p))
// acc += gdup * relu(apair + bpair)
#define AGG_STEP(acc, apair, bpair, gdup) \
    asm("{\n\t.reg .b32 lo, hi;\n\t.reg .b64 t;\n\t" \
        "add.rn.f32x2 t, %1, %2;\n\t" \
        "mov.b64 {lo, hi}, t;\n\t" \
        "max.f32 lo, lo, 0f00000000;\n\t" \
        "max.f32 hi, hi, 0f00000000;\n\t" \
        "mov.b64 t, {lo, hi};\n\t" \
        "fma.rn.f32x2 %0, %3, t, %0;\n\t}" \
        : "+l"(acc) : "l"(apair), "l"(bpair), "l"(gdup))

// ---------------------------------------------------------------------------
// Edge kernel: 2 samples per CTA, 128 threads (all active). (R11 exact)
// ---------------------------------------------------------------------------
struct EdgeSmem {
    float sW2[64*64];           // 16 KB
    float sW1[8*64];            //  2 KB
    float sB[8*GS];             // 17.5 KB : 64 rows in 8 groups ; becomes H
    float sgm[32][GST];         //  4.5 KB dense graph, zero diag + pad rows
    float sx[2][128];           //  1 KB (tail zeroed)
    float scnt[64];             // flat gr = smp*32 + row
    float sb1[64];
    float sb2[64];
};

__global__ __launch_bounds__(128, 5) void edge_kernel(
    const float* __restrict__ data, int mode,
    const float* __restrict__ graph,
    const float* __restrict__ W1, const float* __restrict__ b1,
    const float* __restrict__ W2, const float* __restrict__ b2)
{
    extern __shared__ char smem_raw[];
    EdgeSmem& S = *reinterpret_cast<EdgeSmem*>(smem_raw);

    const int tid = threadIdx.x;
    const int p   = blockIdx.x;
    const int bs  = p >> 5;
    const int c0  = p & 31;

    {
        const float4* w2v = reinterpret_cast<const float4*>(W2);
        float4* d2 = reinterpret_cast<float4*>(S.sW2);
        #pragma unroll
        for (int i = tid; i < 1024; i += 128) d2[i] = w2v[i];
        const float4* w1v = reinterpret_cast<const float4*>(W1);
        float4* d1 = reinterpret_cast<float4*>(S.sW1);
        d1[tid] = w1v[tid];
    }
    if (tid < 64) { S.sb1[tid] = b1[tid]; S.sb2[tid] = b2[tid]; }
    for (int e = tid; e < 900; e += 128) {
        int i = e / 30, j = e - i*30;
        S.sgm[i][j] = (i == j) ? 0.f
                      : graph[(size_t)bs*870 + i*29 + j - (j > i)];
    }
    if (tid < 30) { S.sgm[tid][30] = 0.f; S.sgm[tid][31] = 0.f; }
    if (tid < 64) S.sgm[30 + (tid >> 5)][tid & 31] = 0.f;      // pad g rows
    if (tid < 68) {                                            // zero pad rows
        S.sB[3*GS + 6*AST + tid] = 0.f;   // gr 30
        S.sB[3*GS + 7*AST + tid] = 0.f;   // gr 31
        S.sB[7*GS + 6*AST + tid] = 0.f;   // gr 62
        S.sB[7*GS + 7*AST + tid] = 0.f;   // gr 63
    }
    if (tid < 16) S.sx[tid >> 3][120 + (tid & 7)] = 0.f;       // pad x tail
    if (tid < 4)  S.scnt[((tid >> 1) << 5) + 30 + (tid & 1)] = 0.f;
    for (int v = tid; v < 240; v += 128) {
        int h = v >= 120, idx = v - 120*h;
        int cc = c0 + 32*h, ss = bs*64 + cc;
        S.sx[h][idx] = (mode == 0)
            ? data[((size_t)bs*128 + 2*cc)*120 + idx]
            : g_mu[(size_t)ss*120 + idx];
    }
    __syncthreads();

    // ---- Stage A mapping: smp, rows r0..r0+3 (same sample), cols og..og+7
    const int smp = tid >> 6;
    const int rg  = (tid >> 3) & 7;
    const int cg  = tid & 7;
    const int r0  = rg * 4;
    const int og  = cg * 8;

    ull aA[4][4];               // A-projection, registers
    // ---- projections: A (registers) + B (smem) ----
    {
        float xr[4][4];
        #pragma unroll
        for (int rr = 0; rr < 4; rr++) {
            float4 xv = *reinterpret_cast<const float4*>(&S.sx[smp][(r0+rr)*4]);
            xr[rr][0]=xv.x; xr[rr][1]=xv.y; xr[rr][2]=xv.z; xr[rr][3]=xv.w;
        }
        ull aB[4][4];
        {
            ulonglong2 bq0 = *reinterpret_cast<const ulonglong2*>(&S.sb1[og]);
            ulonglong2 bq1 = *reinterpret_cast<const ulonglong2*>(&S.sb1[og+4]);
            ull bp[4] = {bq0.x, bq0.y, bq1.x, bq1.y};
            #pragma unroll
            for (int rr = 0; rr < 4; rr++)
                #pragma unroll
                for (int q = 0; q < 4; q++) { aA[rr][q] = bp[q]; aB[rr][q] = 0ULL; }
        }
        #pragma unroll
        for (int f = 0; f < 4; f++) {
            ulonglong2 wa0 = *reinterpret_cast<const ulonglong2*>(&S.sW1[f*64+og]);
            ulonglong2 wa1 = *reinterpret_cast<const ulonglong2*>(&S.sW1[f*64+og+4]);
            ulonglong2 wb0 = *reinterpret_cast<const ulonglong2*>(&S.sW1[(f+4)*64+og]);
            ulonglong2 wb1 = *reinterpret_cast<const ulonglong2*>(&S.sW1[(f+4)*64+og+4]);
            ull wa[4] = {wa0.x, wa0.y, wa1.x, wa1.y};
            ull wb[4] = {wb0.x, wb0.y, wb1.x, wb1.y};
            #pragma unroll
            for (int rr = 0; rr < 4; rr++) {
                ull xd; PACKDUP(xd, xr[rr][f]);
                #pragma unroll
                for (int q = 0; q < 4; q++) {
                    FFMA2(aA[rr][q], xd, wa[q]);
                    FFMA2(aB[rr][q], xd, wb[q]);
                }
            }
        }
        #pragma unroll
        for (int rr = 0; rr < 4; rr++) {
            int lr = r0 + rr;
            if (lr < 30) {
                float* dst = S.sB + (smp*4 + (lr>>3))*GS + (lr&7)*AST + og;
                ulonglong2 s0; s0.x = aB[rr][0]; s0.y = aB[rr][1];
                ulonglong2 s1; s1.x = aB[rr][2]; s1.y = aB[rr][3];
                *reinterpret_cast<ulonglong2*>(dst)   = s0;
                *reinterpret_cast<ulonglong2*>(dst+4) = s1;
            }
        }
    }
    __syncthreads();

    // ---- masked-ReLU aggregation: B[j] load serves 4 rows ----
    ull acc[4][4];
    float cnt[4] = {0.f, 0.f, 0.f, 0.f};
    {
        #pragma unroll
        for (int rr = 0; rr < 4; rr++)
            #pragma unroll
            for (int q = 0; q < 4; q++) acc[rr][q] = 0ULL;

        #pragma unroll
        for (int jg = 0; jg < 4; jg++) {
            const float* bg = S.sB + (smp*4 + jg)*GS + og;
            #pragma unroll
            for (int jh = 0; jh < 2; jh++) {
                const int j4 = jg*8 + jh*4;
                float ga[4][4];
                #pragma unroll
                for (int rr = 0; rr < 4; rr++) {
                    float4 gv = *reinterpret_cast<const float4*>(&S.sgm[r0+rr][j4]);
                    ga[rr][0]=gv.x; ga[rr][1]=gv.y; ga[rr][2]=gv.z; ga[rr][3]=gv.w;
                    cnt[rr] += gv.x + gv.y + gv.z + gv.w;
                }
                #pragma unroll
                for (int jj = 0; jj < 4; jj++) {
                    const float* bj = bg + (jh*4 + jj)*AST;
                    ulonglong2 b0 = *reinterpret_cast<const ulonglong2*>(bj);
                    ulonglong2 b1v = *reinterpret_cast<const ulonglong2*>(bj+4);
                    ull bv[4] = {b0.x, b0.y, b1v.x, b1v.y};
                    #pragma unroll
                    for (int rr = 0; rr < 4; rr++) {
                        ull gd; PACKDUP(gd, ga[rr][jj]);
                        #pragma unroll
                        for (int q = 0; q < 4; q++)
                            AGG_STEP(acc[rr][q], aA[rr][q], bv[q], gd);
                    }
                }
            }
        }
    }
    __syncthreads();            // all sB reads complete
    {
        #pragma unroll
        for (int rr = 0; rr < 4; rr++) {
            int lr = r0 + rr;
            if (lr < 30) {
                float* dst = S.sB + (smp*4 + (lr>>3))*GS + (lr&7)*AST + og;
                ulonglong2 s0; s0.x = acc[rr][0]; s0.y = acc[rr][1];
                ulonglong2 s1; s1.x = acc[rr][2]; s1.y = acc[rr][3];
                *reinterpret_cast<ulonglong2*>(dst)   = s0;
                *reinterpret_cast<ulonglong2*>(dst+4) = s1;
            }
        }
        if (cg == 0) {
            #pragma unroll
            for (int rr = 0; rr < 4; rr++)
                if (r0 + rr < 30) S.scnt[smp*32 + r0 + rr] = cnt[rr];
        }
    }
    __syncthreads();

    // ---- Stage B: agg = H @ W2 + cnt*b2. 8 rows x 4 cols per thread. ----
    {
        const int rg2 = tid >> 4;          // 0..7 : group rg2 = rows rg2*8..+7
        const int oc  = (tid & 15) * 4;    // 0..60
        const float* hb = S.sB + rg2*GS;
        ull acc2[8][2];
        {
            ulonglong2 b2p = *reinterpret_cast<const ulonglong2*>(&S.sb2[oc]);
            #pragma unroll
            for (int r = 0; r < 8; r++) {
                ull cd; PACKDUP(cd, S.scnt[rg2*8 + r]);
                MUL2(acc2[r][0], cd, b2p.x);
                MUL2(acc2[r][1], cd, b2p.y);
            }
        }
        #pragma unroll 2
        for (int k4 = 0; k4 < 64; k4 += 4) {
            ulonglong2 w[4];
            #pragma unroll
            for (int kk = 0; kk < 4; kk++)
                w[kk] = *reinterpret_cast<const ulonglong2*>(&S.sW2[(k4+kk)*64 + oc]);
            float4 hv[8];
            #pragma unroll
            for (int r = 0; r < 8; r++)
                hv[r] = *reinterpret_cast<const float4*>(hb + r*AST + k4);
            float ha[8][4];
            #pragma unroll
            for (int r = 0; r < 8; r++) {
                ha[r][0]=hv[r].x; ha[r][1]=hv[r].y; ha[r][2]=hv[r].z; ha[r][3]=hv[r].w;
            }
            #pragma unroll
            for (int kk = 0; kk < 4; kk++) {
                #pragma unroll
                for (int r = 0; r < 8; r++) {
                    ull hd; PACKDUP(hd, ha[r][kk]);
                    FFMA2(acc2[r][0], hd, w[kk].x);
                    FFMA2(acc2[r][1], hd, w[kk].y);
                }
            }
        }
        const int sb0 = bs*64 + c0;
        #pragma unroll
        for (int r = 0; r < 8; r++) {
            int gr = rg2*8 + r;
            int sm2 = gr >> 5, row = gr & 31;
            if (row < 30) {
                size_t base = ((size_t)(sb0 + 32*sm2)*NN + row)*HH + oc;
                ulonglong2 st; st.x = acc2[r][0]; st.y = acc2[r][1];
                *reinterpret_cast<ulonglong2*>(&g_agg[base]) = st;
            }
        }
    }
}

// ---------------------------------------------------------------------------
// Node MLP kernel: 64 ->relu-> 64 ->relu-> 64 -> 4. 8 samples/CTA, 256 thr
// (240 active = 30 row-groups x 8 col-groups; per-thread body identical to
// the 53us champion). Single weight buffer with mid-kernel W2 reload.
// 2 CTAs/SM -> 16 warps/SM; grid 512 -> 1.73 waves.
// ---------------------------------------------------------------------------
struct NodeSmem {
    float sW[64*64];            // 16 KB, W1 then W2
    float sW3[64*4];
    float buf[30*GS];           // 65.8 KB : 240 rows in 30 groups of 8
    float sb1[64];
    float sb2[64];
    float sb3[8];
};

__device__ __forceinline__ void gemm8_compute(
    const float* __restrict__ r0,      // &buf[ig*GS]
    const float* __restrict__ sW, const float* __restrict__ sb,
    int og, ull acc[8][4])
{
    {
        ulonglong2 bq0 = *reinterpret_cast<const ulonglong2*>(&sb[og]);
        ulonglong2 bq1 = *reinterpret_cast<const ulonglong2*>(&sb[og+4]);
        ull bp[4] = {bq0.x, bq0.y, bq1.x, bq1.y};
        #pragma unroll
        for (int r = 0; r < 8; r++)
            #pragma unroll
            for (int q = 0; q < 4; q++) acc[r][q] = bp[q];
    }
    #pragma unroll 2
    for (int k4 = 0; k4 < 64; k4 += 4) {
        float4 hv[8];
        #pragma unroll
        for (int r = 0; r < 8; r++)
            hv[r] = *reinterpret_cast<const float4*>(r0 + r*AST + k4);
        float ha[8][4];
        #pragma unroll
        for (int r = 0; r < 8; r++) {
            ha[r][0]=hv[r].x; ha[r][1]=hv[r].y; ha[r][2]=hv[r].z; ha[r][3]=hv[r].w;
        }
        #pragma unroll
        for (int kk = 0; kk < 4; kk++) {
            ulonglong2 w0 = *reinterpret_cast<const ulonglong2*>(&sW[(k4+kk)*64+og]);
            ulonglong2 w1 = *reinterpret_cast<const ulonglong2*>(&sW[(k4+kk)*64+og+4]);
            ull wv[4] = {w0.x, w0.y, w1.x, w1.y};
            #pragma unroll
            for (int r = 0; r < 8; r++) {
                ull hd; PACKDUP(hd, ha[r][kk]);
                #pragma unroll
                for (int q = 0; q < 4; q++) FFMA2(acc[r][q], hd, wv[q]);
            }
        }
    }
}

__device__ __forceinline__ void gemm8_store_relu(
    float* __restrict__ w0, ull acc[8][4])   // w0 = &buf[ig*GS + og]
{
    #pragma unroll
    for (int r = 0; r < 8; r++) {
        float* dst = w0 + r*AST;
        float x0,x1,x2,x3,x4,x5,x6,x7;
        UNPACK2(x0,x1,acc[r][0]); UNPACK2(x2,x3,acc[r][1]);
        UNPACK2(x4,x5,acc[r][2]); UNPACK2(x6,x7,acc[r][3]);
        *reinterpret_cast<float4*>(dst) =
            make_float4(fmaxf(x0,0.f),fmaxf(x1,0.f),fmaxf(x2,0.f),fmaxf(x3,0.f));
        *reinterpret_cast<float4*>(dst+4) =
            make_float4(fmaxf(x4,0.f),fmaxf(x5,0.f),fmaxf(x6,0.f),fmaxf(x7,0.f));
    }
}

__global__ __launch_bounds__(256, 2) void node_kernel(
    const float* __restrict__ mW1, const float* __restrict__ mb1,
    const float* __restrict__ mW2, const float* __restrict__ mb2,
    const float* __restrict__ mW3, const float* __restrict__ mb3,
    const float* __restrict__ vW1, const float* __restrict__ vb1,
    const float* __restrict__ vW2, const float* __restrict__ vb2,
    const float* __restrict__ vW3, const float* __restrict__ vb3,
    float* __restrict__ out, int t)
{
    extern __shared__ char smem_raw[];
    NodeSmem& S = *reinterpret_cast<NodeSmem*>(smem_raw);

    const int tid = threadIdx.x;
    const int p   = blockIdx.x;       // 0..255
    const int is_var = blockIdx.y;
    const int bs  = p >> 3;           // 0..31
    const int c0  = p & 7;            // samples c0 + 8*smp, smp = 0..7

    const float* W1 = is_var ? vW1 : mW1;
    const float* W2 = is_var ? vW2 : mW2;
    const float* W3 = is_var ? vW3 : mW3;
    const float* b1 = is_var ? vb1 : mb1;
    const float* b2 = is_var ? vb2 : mb2;
    const float* b3 = is_var ? vb3 : mb3;

    {
        const float4* w1v = reinterpret_cast<const float4*>(W1);
        float4* s1 = reinterpret_cast<float4*>(S.sW);
        #pragma unroll
        for (int i = tid; i < 1024; i += 256) s1[i] = w1v[i];
        S.sW3[tid] = W3[tid];                 // exactly 256 floats
    }
    if (tid < 64) { S.sb1[tid] = b1[tid]; S.sb2[tid] = b2[tid]; }
    if (tid < 4)  S.sb3[tid] = b3[tid];
    if (tid >= 4 && tid < 8) S.sb3[tid] = 0.f;

    // load 8 samples of agg: 3840 float4, 15 per thread
    {
        const float4* ab = reinterpret_cast<const float4*>(g_agg);
        #pragma unroll
        for (int v = tid; v < 3840; v += 256) {
            int smp = v / 480, vv = v - smp*480;
            int row = vv >> 4, cp = vv & 15;
            int inst = smp*30 + row;
            float4 val = ab[(size_t)(bs*64 + c0 + 8*smp)*480 + vv];
            *reinterpret_cast<float4*>(&S.buf[(inst>>3)*GS + (inst&7)*AST + cp*4]) = val;
        }
    }
    __syncthreads();

    const int ig = tid >> 3, cg = tid & 7;    // ig 0..31 (0..29 active)
    const int og = cg*8;
    const float* r0 = &S.buf[ig*GS];
    float*       w0 = &S.buf[ig*GS + og];

    ull acc[8][4];
    // Layer 1 (sW = W1)
    if (tid < 240) gemm8_compute(r0, S.sW, S.sb1, og, acc);
    __syncthreads();
    if (tid < 240) gemm8_store_relu(w0, acc);
    {
        const float4* w2v = reinterpret_cast<const float4*>(W2);
        float4* s1 = reinterpret_cast<float4*>(S.sW);
        #pragma unroll
        for (int i = tid; i < 1024; i += 256) s1[i] = w2v[i];
    }
    __syncthreads();
    // Layer 2 (sW = W2)
    if (tid < 240) gemm8_compute(r0, S.sW, S.sb2, og, acc);
    __syncthreads();
    if (tid < 240) gemm8_store_relu(w0, acc);
    __syncthreads();

    // Layer 3: 64 -> 4. 240 threads, one instance each.
    if (tid < 240) {
        const int smp = tid / 30, n = tid - smp*30;
        const float* hr = &S.buf[(tid>>3)*GS + (tid&7)*AST];
        ulonglong2 b3q = *reinterpret_cast<const ulonglong2*>(&S.sb3[0]);
        ull a01 = b3q.x, a23 = b3q.y;
        #pragma unroll 4
        for (int k4 = 0; k4 < 64; k4 += 4) {
            float4 hv = *reinterpret_cast<const float4*>(hr + k4);
            float ha[4] = {hv.x, hv.y, hv.z, hv.w};
            #pragma unroll
            for (int kk = 0; kk < 4; kk++) {
                ulonglong2 w = *reinterpret_cast<const ulonglong2*>(&S.sW3[(k4+kk)*4]);
                ull hd; PACKDUP(hd, ha[kk]);
                FFMA2(a01, hd, w.x);
                FFMA2(a23, hd, w.y);
            }
        }
        float v0,v1,v2,v3;
        UNPACK2(v0,v1,a01); UNPACK2(v2,v3,a23);
        float v[4] = {v0,v1,v2,v3};
        if (is_var) {
            #pragma unroll
            for (int q = 0; q < 4; q++) {
                float x = v[q];
                float sp = (x > 20.f) ? x : log1pf(expf(x));
                v[q] = fminf(fmaxf(sp, 1e-8f), 100.f);
            }
        }
        const int c = c0 + 8*smp;
        const int s = bs*64 + c;
        if (!is_var && t == 0)
            *reinterpret_cast<float4*>(&g_mu[(size_t)s*120 + n*4]) =
                make_float4(v[0],v[1],v[2],v[3]);
        const int kt = 2*c + t;
        if (kt < TOUT) {
            size_t o = (((size_t)bs*TOUT + kt)*NN + n)*FF;
            *reinterpret_cast<float4*>(&out[o + (is_var ? (size_t)VAROFF : 0)]) =
                make_float4(v[0],v[1],v[2],v[3]);
        }
    }
}

// ---------------------------------------------------------------------------
extern "C" void kernel_launch(void* const* d_in, const int* in_sizes, int n_in,
                              void* d_out, int out_size) {
    const float* data    = (const float*)d_in[0];
    const float* graph   = (const float*)d_in[1];
    const float* msg_W1  = (const float*)d_in[2];
    const float* msg_b1  = (const float*)d_in[3];
    const float* msg_W2  = (const float*)d_in[4];
    const float* msg_b2  = (const float*)d_in[5];
    const float* mean_W1 = (const float*)d_in[6];
    const float* mean_b1 = (const float*)d_in[7];
    const float* mean_W2 = (const float*)d_in[8];
    const float* mean_b2 = (const float*)d_in[9];
    const float* mean_W3 = (const float*)d_in[10];
    const float* mean_b3 = (const float*)d_in[11];
    const float* var_W1  = (const float*)d_in[12];
    const float* var_b1  = (const float*)d_in[13];
    const float* var_W2  = (const float*)d_in[14];
    const float* var_b2  = (const float*)d_in[15];
    const float* var_W3  = (const float*)d_in[16];
    const float* var_b3  = (const float*)d_in[17];
    float* out = (float*)d_out;

    cudaFuncSetAttribute(edge_kernel, cudaFuncAttributeMaxDynamicSharedMemorySize,
                         (int)sizeof(EdgeSmem));
    cudaFuncSetAttribute(node_kernel, cudaFuncAttributeMaxDynamicSharedMemorySize,
                         (int)sizeof(NodeSmem));

    dim3 ngrid(NSAMP/8, 2);
    for (int t = 0; t < 2; t++) {
        edge_kernel<<<NSAMP/2, 128, sizeof(EdgeSmem)>>>(data, t, graph,
                                    msg_W1, msg_b1, msg_W2, msg_b2);
        node_kernel<<<ngrid, 256, sizeof(NodeSmem)>>>(
            mean_W1, mean_b1, mean_W2, mean_b2, mean_W3, mean_b3,
            var_W1,  var_b1,  var_W2,  var_b2,  var_W3,  var_b3,
            out, t);
    }
}

// round 15
// speedup vs baseline: 1.1170x; 1.1170x over previous
#include <cuda_runtime.h>
#include <math.h>

typedef unsigned long long ull;

#define NN 30
#define FF 4
#define HH 64
#define NSAMP 2048          // 32 * 64
#define TOUT 127
#define VAROFF (32*127*30*4)
#define AST 68              // activation row stride (floats), bank-staggered
#define GS  (8*AST + 4)     // 548: 8-row group stride; +4 staggers groups across banks
#define GST 36              // dense-graph row stride (floats), bank-staggered

// Scratch (allocation-free rule: __device__ globals)
__device__ float g_agg[(size_t)NSAMP * NN * HH];   // 15.7 MB
__device__ float g_mu [(size_t)NSAMP * NN * FF];   // 0.98 MB

// ---- packed f32x2 helpers (sm_103a) ---------------------------------------
#define FFMA2(acc, a, b) \
    asm("fma.rn.f32x2 %0, %1, %2, %0;" : "+l"(acc) : "l"(a), "l"(b))
#define MUL2(d, a, b) \
    asm("mul.rn.f32x2 %0, %1, %2;" : "=l"(d) : "l"(a), "l"(b))
#define PACKDUP(d, x) \
    asm("mov.b64 %0, {%1, %1};" : "=l"(d) : "r"(__float_as_uint(x)))
#define UNPACK2(x, y, p) \
    asm("mov.b64 {%0, %1}, %2;" : "=f"(x), "=f"(y) : "l"(p))
// acc += gdup * relu(apair + bpair)
#define AGG_STEP(acc, apair, bpair, gdup) \
    asm("{\n\t.reg .b32 lo, hi;\n\t.reg .b64 t;\n\t" \
        "add.rn.f32x2 t, %1, %2;\n\t" \
        "mov.b64 {lo, hi}, t;\n\t" \
        "max.f32 lo, lo, 0f00000000;\n\t" \
        "max.f32 hi, hi, 0f00000000;\n\t" \
        "mov.b64 t, {lo, hi};\n\t" \
        "fma.rn.f32x2 %0, %3, t, %0;\n\t}" \
        : "+l"(acc) : "l"(apair), "l"(bpair), "l"(gdup))

// PDL intrinsics (sm_90+): wait for prior grid's writes / release dependent grid
#define GRID_DEP_SYNC()  cudaGridDependencySynchronize()
#define GRID_TRIGGER()   cudaTriggerProgrammaticLaunchCompletion()

// ---------------------------------------------------------------------------
// Edge kernel: 2 samples per CTA, 128 threads (all active). (R11 body + PDL)
// sB is flat with group-padded rows: row gr (0..63) at (gr>>3)*GS+(gr&7)*AST.
// Stage A: thread = (smp, 4-row group, 8 cols). Stage B: (8-row group, 4 cols).
// H overwrites sB in place between stages.
// ---------------------------------------------------------------------------
struct EdgeSmem {
    float sW2[64*64];           // 16 KB
    float sW1[8*64];            //  2 KB
    float sB[8*GS];             // 17.5 KB : 64 rows in 8 groups ; becomes H
    float sgm[32][GST];         //  4.5 KB dense graph, zero diag + pad rows
    float sx[2][128];           //  1 KB (tail zeroed)
    float scnt[64];             // flat gr = smp*32 + row
    float sb1[64];
    float sb2[64];
};

__global__ __launch_bounds__(128, 5) void edge_kernel(
    const float* __restrict__ data, int mode,
    const float* __restrict__ graph,
    const float* __restrict__ W1, const float* __restrict__ b1,
    const float* __restrict__ W2, const float* __restrict__ b2)
{
    extern __shared__ char smem_raw[];
    EdgeSmem& S = *reinterpret_cast<EdgeSmem*>(smem_raw);

    const int tid = threadIdx.x;
    const int p   = blockIdx.x;
    const int bs  = p >> 5;
    const int c0  = p & 31;

    // ---- dependency-free prologue: weights, biases, graph, padding ----
    {
        const float4* w2v = reinterpret_cast<const float4*>(W2);
        float4* d2 = reinterpret_cast<float4*>(S.sW2);
        #pragma unroll
        for (int i = tid; i < 1024; i += 128) d2[i] = w2v[i];
        const float4* w1v = reinterpret_cast<const float4*>(W1);
        float4* d1 = reinterpret_cast<float4*>(S.sW1);
        d1[tid] = w1v[tid];
    }
    if (tid < 64) { S.sb1[tid] = b1[tid]; S.sb2[tid] = b2[tid]; }
    for (int e = tid; e < 900; e += 128) {
        int i = e / 30, j = e - i*30;
        S.sgm[i][j] = (i == j) ? 0.f
                      : graph[(size_t)bs*870 + i*29 + j - (j > i)];
    }
    if (tid < 30) { S.sgm[tid][30] = 0.f; S.sgm[tid][31] = 0.f; }
    if (tid < 64) S.sgm[30 + (tid >> 5)][tid & 31] = 0.f;      // pad g rows
    if (tid < 68) {                                            // zero pad rows
        S.sB[3*GS + 6*AST + tid] = 0.f;   // gr 30
        S.sB[3*GS + 7*AST + tid] = 0.f;   // gr 31
        S.sB[7*GS + 6*AST + tid] = 0.f;   // gr 62
        S.sB[7*GS + 7*AST + tid] = 0.f;   // gr 63
    }
    if (tid < 16) S.sx[tid >> 3][120 + (tid & 7)] = 0.f;       // pad x tail
    if (tid < 4)  S.scnt[((tid >> 1) << 5) + 30 + (tid & 1)] = 0.f;

    // ---- dependent read (g_mu in mode 1) happens only after prior grid done
    GRID_DEP_SYNC();
    for (int v = tid; v < 240; v += 128) {
        int h = v >= 120, idx = v - 120*h;
        int cc = c0 + 32*h, ss = bs*64 + cc;
        S.sx[h][idx] = (mode == 0)
            ? data[((size_t)bs*128 + 2*cc)*120 + idx]
            : g_mu[(size_t)ss*120 + idx];
    }
    __syncthreads();

    // ---- Stage A mapping: smp, rows r0..r0+3 (same sample), cols og..og+7
    const int smp = tid >> 6;
    const int rg  = (tid >> 3) & 7;
    const int cg  = tid & 7;
    const int r0  = rg * 4;
    const int og  = cg * 8;

    ull aA[4][4];               // A-projection, registers
    // ---- projections: A (registers) + B (smem) ----
    {
        float xr[4][4];
        #pragma unroll
        for (int rr = 0; rr < 4; rr++) {
            float4 xv = *reinterpret_cast<const float4*>(&S.sx[smp][(r0+rr)*4]);
            xr[rr][0]=xv.x; xr[rr][1]=xv.y; xr[rr][2]=xv.z; xr[rr][3]=xv.w;
        }
        ull aB[4][4];
        {
            ulonglong2 bq0 = *reinterpret_cast<const ulonglong2*>(&S.sb1[og]);
            ulonglong2 bq1 = *reinterpret_cast<const ulonglong2*>(&S.sb1[og+4]);
            ull bp[4] = {bq0.x, bq0.y, bq1.x, bq1.y};
            #pragma unroll
            for (int rr = 0; rr < 4; rr++)
                #pragma unroll
                for (int q = 0; q < 4; q++) { aA[rr][q] = bp[q]; aB[rr][q] = 0ULL; }
        }
        #pragma unroll
        for (int f = 0; f < 4; f++) {
            ulonglong2 wa0 = *reinterpret_cast<const ulonglong2*>(&S.sW1[f*64+og]);
            ulonglong2 wa1 = *reinterpret_cast<const ulonglong2*>(&S.sW1[f*64+og+4]);
            ulonglong2 wb0 = *reinterpret_cast<const ulonglong2*>(&S.sW1[(f+4)*64+og]);
            ulonglong2 wb1 = *reinterpret_cast<const ulonglong2*>(&S.sW1[(f+4)*64+og+4]);
            ull wa[4] = {wa0.x, wa0.y, wa1.x, wa1.y};
            ull wb[4] = {wb0.x, wb0.y, wb1.x, wb1.y};
            #pragma unroll
            for (int rr = 0; rr < 4; rr++) {
                ull xd; PACKDUP(xd, xr[rr][f]);
                #pragma unroll
                for (int q = 0; q < 4; q++) {
                    FFMA2(aA[rr][q], xd, wa[q]);
                    FFMA2(aB[rr][q], xd, wb[q]);
                }
            }
        }
        #pragma unroll
        for (int rr = 0; rr < 4; rr++) {
            int lr = r0 + rr;
            if (lr < 30) {
                float* dst = S.sB + (smp*4 + (lr>>3))*GS + (lr&7)*AST + og;
                ulonglong2 s0; s0.x = aB[rr][0]; s0.y = aB[rr][1];
                ulonglong2 s1; s1.x = aB[rr][2]; s1.y = aB[rr][3];
                *reinterpret_cast<ulonglong2*>(dst)   = s0;
                *reinterpret_cast<ulonglong2*>(dst+4) = s1;
            }
        }
    }
    __syncthreads();

    // ---- masked-ReLU aggregation: B[j] load serves 4 rows ----
    ull acc[4][4];
    float cnt[4] = {0.f, 0.f, 0.f, 0.f};
    {
        #pragma unroll
        for (int rr = 0; rr < 4; rr++)
            #pragma unroll
            for (int q = 0; q < 4; q++) acc[rr][q] = 0ULL;

        #pragma unroll
        for (int jg = 0; jg < 4; jg++) {
            const float* bg = S.sB + (smp*4 + jg)*GS + og;
            #pragma unroll
            for (int jh = 0; jh < 2; jh++) {
                const int j4 = jg*8 + jh*4;
                float ga[4][4];
                #pragma unroll
                for (int rr = 0; rr < 4; rr++) {
                    float4 gv = *reinterpret_cast<const float4*>(&S.sgm[r0+rr][j4]);
                    ga[rr][0]=gv.x; ga[rr][1]=gv.y; ga[rr][2]=gv.z; ga[rr][3]=gv.w;
                    cnt[rr] += gv.x + gv.y + gv.z + gv.w;
                }
                #pragma unroll
                for (int jj = 0; jj < 4; jj++) {
                    const float* bj = bg + (jh*4 + jj)*AST;
                    ulonglong2 b0 = *reinterpret_cast<const ulonglong2*>(bj);
                    ulonglong2 b1v = *reinterpret_cast<const ulonglong2*>(bj+4);
                    ull bv[4] = {b0.x, b0.y, b1v.x, b1v.y};
                    #pragma unroll
                    for (int rr = 0; rr < 4; rr++) {
                        ull gd; PACKDUP(gd, ga[rr][jj]);
                        #pragma unroll
                        for (int q = 0; q < 4; q++)
                            AGG_STEP(acc[rr][q], aA[rr][q], bv[q], gd);
                    }
                }
            }
        }
    }
    __syncthreads();            // all sB reads complete
    {
        #pragma unroll
        for (int rr = 0; rr < 4; rr++) {
            int lr = r0 + rr;
            if (lr < 30) {
                float* dst = S.sB + (smp*4 + (lr>>3))*GS + (lr&7)*AST + og;
                ulonglong2 s0; s0.x = acc[rr][0]; s0.y = acc[rr][1];
                ulonglong2 s1; s1.x = acc[rr][2]; s1.y = acc[rr][3];
                *reinterpret_cast<ulonglong2*>(dst)   = s0;
                *reinterpret_cast<ulonglong2*>(dst+4) = s1;
            }
        }
        if (cg == 0) {
            #pragma unroll
            for (int rr = 0; rr < 4; rr++)
                if (r0 + rr < 30) S.scnt[smp*32 + r0 + rr] = cnt[rr];
        }
    }
    __syncthreads();
    GRID_TRIGGER();             // only Stage B compute remains -> release dependent

    // ---- Stage B: agg = H @ W2 + cnt*b2. 8 rows x 4 cols per thread. ----
    {
        const int rg2 = tid >> 4;          // 0..7 : group rg2 = rows rg2*8..+7
        const int oc  = (tid & 15) * 4;    // 0..60
        const float* hb = S.sB + rg2*GS;
        ull acc2[8][2];
        {
            ulonglong2 b2p = *reinterpret_cast<const ulonglong2*>(&S.sb2[oc]);
            #pragma unroll
            for (int r = 0; r < 8; r++) {
                ull cd; PACKDUP(cd, S.scnt[rg2*8 + r]);
                MUL2(acc2[r][0], cd, b2p.x);
                MUL2(acc2[r][1], cd, b2p.y);
            }
        }
        #pragma unroll 2
        for (int k4 = 0; k4 < 64; k4 += 4) {
            ulonglong2 w[4];
            #pragma unroll
            for (int kk = 0; kk < 4; kk++)
                w[kk] = *reinterpret_cast<const ulonglong2*>(&S.sW2[(k4+kk)*64 + oc]);
            float4 hv[8];
            #pragma unroll
            for (int r = 0; r < 8; r++)
                hv[r] = *reinterpret_cast<const float4*>(hb + r*AST + k4);
            float ha[8][4];
            #pragma unroll
            for (int r = 0; r < 8; r++) {
                ha[r][0]=hv[r].x; ha[r][1]=hv[r].y; ha[r][2]=hv[r].z; ha[r][3]=hv[r].w;
            }
            #pragma unroll
            for (int kk = 0; kk < 4; kk++) {
                #pragma unroll
                for (int r = 0; r < 8; r++) {
                    ull hd; PACKDUP(hd, ha[r][kk]);
                    FFMA2(acc2[r][0], hd, w[kk].x);
                    FFMA2(acc2[r][1], hd, w[kk].y);
                }
            }
        }
        const int sb0 = bs*64 + c0;
        #pragma unroll
        for (int r = 0; r < 8; r++) {
            int gr = rg2*8 + r;
            int sm2 = gr >> 5, row = gr & 31;
            if (row < 30) {
                size_t base = ((size_t)(sb0 + 32*sm2)*NN + row)*HH + oc;
                ulonglong2 st; st.x = acc2[r][0]; st.y = acc2[r][1];
                *reinterpret_cast<ulonglong2*>(&g_agg[base]) = st;
            }
        }
    }
}

// ---------------------------------------------------------------------------
// Node MLP kernel: 64 ->relu-> 64 ->relu-> 64 -> 4. 4 samples/CTA, 128 thr.
// R11 champion body + PDL: weights load before GRID_DEP_SYNC, g_agg after.
// ---------------------------------------------------------------------------
struct NodeSmem {
    float sW[64*64];            // 16 KB, W1 then W2
    float sW3[64*4];
    float buf[15*GS];           // 32.1 KB : 120 rows in 15 groups of 8
    float sb1[64];
    float sb2[64];
    float sb3[8];
};

__device__ __forceinline__ void gemm8_compute(
    const float* __restrict__ r0,      // &buf[ig*GS]
    const float* __restrict__ sW, const float* __restrict__ sb,
    int og, ull acc[8][4])
{
    {
        ulonglong2 bq0 = *reinterpret_cast<const ulonglong2*>(&sb[og]);
        ulonglong2 bq1 = *reinterpret_cast<const ulonglong2*>(&sb[og+4]);
        ull bp[4] = {bq0.x, bq0.y, bq1.x, bq1.y};
        #pragma unroll
        for (int r = 0; r < 8; r++)
            #pragma unroll
            for (int q = 0; q < 4; q++) acc[r][q] = bp[q];
    }
    #pragma unroll 2
    for (int k4 = 0; k4 < 64; k4 += 4) {
        float4 hv[8];
        #pragma unroll
        for (int r = 0; r < 8; r++)
            hv[r] = *reinterpret_cast<const float4*>(r0 + r*AST + k4);
        float ha[8][4];
        #pragma unroll
        for (int r = 0; r < 8; r++) {
            ha[r][0]=hv[r].x; ha[r][1]=hv[r].y; ha[r][2]=hv[r].z; ha[r][3]=hv[r].w;
        }
        #pragma unroll
        for (int kk = 0; kk < 4; kk++) {
            ulonglong2 w0 = *reinterpret_cast<const ulonglong2*>(&sW[(k4+kk)*64+og]);
            ulonglong2 w1 = *reinterpret_cast<const ulonglong2*>(&sW[(k4+kk)*64+og+4]);
            ull wv[4] = {w0.x, w0.y, w1.x, w1.y};
            #pragma unroll
            for (int r = 0; r < 8; r++) {
                ull hd; PACKDUP(hd, ha[r][kk]);
                #pragma unroll
                for (int q = 0; q < 4; q++) FFMA2(acc[r][q], hd, wv[q]);
            }
        }
    }
}

__device__ __forceinline__ void gemm8_store_relu(
    float* __restrict__ w0, ull acc[8][4])   // w0 = &buf[ig*GS + og]
{
    #pragma unroll
    for (int r = 0; r < 8; r++) {
        float* dst = w0 + r*AST;
        float x0,x1,x2,x3,x4,x5,x6,x7;
        UNPACK2(x0,x1,acc[r][0]); UNPACK2(x2,x3,acc[r][1]);
        UNPACK2(x4,x5,acc[r][2]); UNPACK2(x6,x7,acc[r][3]);
        *reinterpret_cast<float4*>(dst) =
            make_float4(fmaxf(x0,0.f),fmaxf(x1,0.f),fmaxf(x2,0.f),fmaxf(x3,0.f));
        *reinterpret_cast<float4*>(dst+4) =
            make_float4(fmaxf(x4,0.f),fmaxf(x5,0.f),fmaxf(x6,0.f),fmaxf(x7,0.f));
    }
}

__global__ __launch_bounds__(128, 3) void node_kernel(
    const float* __restrict__ mW1, const float* __restrict__ mb1,
    const float* __restrict__ mW2, const float* __restrict__ mb2,
    const float* __restrict__ mW3, const float* __restrict__ mb3,
    const float* __restrict__ vW1, const float* __restrict__ vb1,
    const float* __restrict__ vW2, const float* __restrict__ vb2,
    const float* __restrict__ vW3, const float* __restrict__ vb3,
    float* __restrict__ out, int t)
{
    extern __shared__ char smem_raw[];
    NodeSmem& S = *reinterpret_cast<NodeSmem*>(smem_raw);

    const int tid = threadIdx.x;
    const int p   = blockIdx.x;       // 0..511
    const int is_var = blockIdx.y;
    const int bs  = p >> 4;           // 0..31
    const int c0  = p & 15;           // samples c0 + 16*smp

    const float* W1 = is_var ? vW1 : mW1;
    const float* W2 = is_var ? vW2 : mW2;
    const float* W3 = is_var ? vW3 : mW3;
    const float* b1 = is_var ? vb1 : mb1;
    const float* b2 = is_var ? vb2 : mb2;
    const float* b3 = is_var ? vb3 : mb3;

    // ---- dependency-free prologue: W1 + W3 + biases ----
    {
        const float4* w1v = reinterpret_cast<const float4*>(W1);
        float4* s1 = reinterpret_cast<float4*>(S.sW);
        #pragma unroll
        for (int i = tid; i < 1024; i += 128) s1[i] = w1v[i];
        S.sW3[tid] = W3[tid]; S.sW3[tid+128] = W3[tid+128];
    }
    if (tid < 64) { S.sb1[tid] = b1[tid]; S.sb2[tid] = b2[tid]; }
    if (tid < 4)  S.sb3[tid] = b3[tid];
    if (tid >= 4 && tid < 8) S.sb3[tid] = 0.f;

    // ---- dependent read: g_agg written by edge kernel ----
    GRID_DEP_SYNC();
    {
        const float4* ab = reinterpret_cast<const float4*>(g_agg);
        #pragma unroll
        for (int v = tid; v < 1920; v += 128) {
            int smp = v / 480, vv = v - smp*480;
            int row = vv >> 4, cp = vv & 15;
            int inst = smp*30 + row;
            float4 val = ab[(size_t)(bs*64 + c0 + 16*smp)*480 + vv];
            *reinterpret_cast<float4*>(&S.buf[(inst>>3)*GS + (inst&7)*AST + cp*4]) = val;
        }
    }
    __syncthreads();

    const int ig = tid >> 3, cg = tid & 7;
    const int og = cg*8;
    const float* r0 = &S.buf[ig*GS];
    float*       w0 = &S.buf[ig*GS + og];

    ull acc[8][4];
    // Layer 1 (sW = W1)
    if (tid < 120) gemm8_compute(r0, S.sW, S.sb1, og, acc);
    __syncthreads();
    if (tid < 120) gemm8_store_relu(w0, acc);
    {
        const float4* w2v = reinterpret_cast<const float4*>(W2);
        float4* s1 = reinterpret_cast<float4*>(S.sW);
        #pragma unroll
        for (int i = tid; i < 1024; i += 128) s1[i] = w2v[i];
    }
    __syncthreads();
    // Layer 2 (sW = W2)
    if (tid < 120) gemm8_compute(r0, S.sW, S.sb2, og, acc);
    __syncthreads();
    if (tid < 120) gemm8_store_relu(w0, acc);
    __syncthreads();
    GRID_TRIGGER();             // only layer 3 + stores remain -> release dependent

    // Layer 3: 64 -> 4. 120 threads, one instance each.
    if (tid < 120) {
        const int smp = tid / 30, n = tid - smp*30;
        const float* hr = &S.buf[(tid>>3)*GS + (tid&7)*AST];
        ulonglong2 b3q = *reinterpret_cast<const ulonglong2*>(&S.sb3[0]);
        ull a01 = b3q.x, a23 = b3q.y;
        #pragma unroll 4
        for (int k4 = 0; k4 < 64; k4 += 4) {
            float4 hv = *reinterpret_cast<const float4*>(hr + k4);
            float ha[4] = {hv.x, hv.y, hv.z, hv.w};
            #pragma unroll
            for (int kk = 0; kk < 4; kk++) {
                ulonglong2 w = *reinterpret_cast<const ulonglong2*>(&S.sW3[(k4+kk)*4]);
                ull hd; PACKDUP(hd, ha[kk]);
                FFMA2(a01, hd, w.x);
                FFMA2(a23, hd, w.y);
            }
        }
        float v0,v1,v2,v3;
        UNPACK2(v0,v1,a01); UNPACK2(v2,v3,a23);
        float v[4] = {v0,v1,v2,v3};
        if (is_var) {
            #pragma unroll
            for (int q = 0; q < 4; q++) {
                float x = v[q];
                float sp = (x > 20.f) ? x : log1pf(expf(x));
                v[q] = fminf(fmaxf(sp, 1e-8f), 100.f);
            }
        }
        const int c = c0 + 16*smp;
        const int s = bs*64 + c;
        if (!is_var && t == 0)
            *reinterpret_cast<float4*>(&g_mu[(size_t)s*120 + n*4]) =
                make_float4(v[0],v[1],v[2],v[3]);
        const int kt = 2*c + t;
        if (kt < TOUT) {
            size_t o = (((size_t)bs*TOUT + kt)*NN + n)*FF;
            *reinterpret_cast<float4*>(&out[o + (is_var ? (size_t)VAROFF : 0)]) =
                make_float4(v[0],v[1],v[2],v[3]);
        }
    }
}

// ---------------------------------------------------------------------------
extern "C" void kernel_launch(void* const* d_in, const int* in_sizes, int n_in,
                              void* d_out, int out_size) {
    const float* data    = (const float*)d_in[0];
    const float* graph   = (const float*)d_in[1];
    const float* msg_W1  = (const float*)d_in[2];
    const float* msg_b1  = (const float*)d_in[3];
    const float* msg_W2  = (const float*)d_in[4];
    const float* msg_b2  = (const float*)d_in[5];
    const float* mean_W1 = (const float*)d_in[6];
    const float* mean_b1 = (const float*)d_in[7];
    const float* mean_W2 = (const float*)d_in[8];
    const float* mean_b2 = (const float*)d_in[9];
    const float* mean_W3 = (const float*)d_in[10];
    const float* mean_b3 = (const float*)d_in[11];
    const float* var_W1  = (const float*)d_in[12];
    const float* var_b1  = (const float*)d_in[13];
    const float* var_W2  = (const float*)d_in[14];
    const float* var_b2  = (const float*)d_in[15];
    const float* var_W3  = (const float*)d_in[16];
    const float* var_b3  = (const float*)d_in[17];
    float* out = (float*)d_out;

    cudaFuncSetAttribute(edge_kernel, cudaFuncAttributeMaxDynamicSharedMemorySize,
                         (int)sizeof(EdgeSmem));
    cudaFuncSetAttribute(node_kernel, cudaFuncAttributeMaxDynamicSharedMemorySize,
                         (int)sizeof(NodeSmem));

    // PDL launch configs: programmatic stream serialization on every launch
    cudaLaunchAttribute attrs[1];
    attrs[0].id = cudaLaunchAttributeProgrammaticStreamSerialization;
    attrs[0].val.programmaticStreamSerializationAllowed = 1;

    cudaLaunchConfig_t ecfg = {};
    ecfg.gridDim  = dim3(NSAMP/2, 1, 1);
    ecfg.blockDim = dim3(128, 1, 1);
    ecfg.dynamicSmemBytes = sizeof(EdgeSmem);
    ecfg.stream = 0;
    ecfg.attrs = attrs; ecfg.numAttrs = 1;

    cudaLaunchConfig_t ncfg = {};
    ncfg.gridDim  = dim3(NSAMP/4, 2, 1);
    ncfg.blockDim = dim3(128, 1, 1);
    ncfg.dynamicSmemBytes = sizeof(NodeSmem);
    ncfg.stream = 0;
    ncfg.attrs = attrs; ncfg.numAttrs = 1;

    for (int t = 0; t < 2; t++) {
        cudaLaunchKernelEx(&ecfg, edge_kernel, data, t, graph,
                           msg_W1, msg_b1, msg_W2, msg_b2);
        cudaLaunchKernelEx(&ncfg, node_kernel,
                           mean_W1, mean_b1, mean_W2, mean_b2, mean_W3, mean_b3,
                           var_W1,  var_b1,  var_W2,  var_b2,  var_W3,  var_b3,
                           out, t);
    }
}

// round 16
// speedup vs baseline: 1.1242x; 1.0065x over previous
#include <cuda_runtime.h>
#include <math.h>

typedef unsigned long long ull;

#define NN 30
#define FF 4
#define HH 64
#define NSAMP 2048          // 32 * 64
#define TOUT 127
#define VAROFF (32*127*30*4)
#define AST 68              // activation row stride (floats), bank-staggered
#define GS  (8*AST + 4)     // 548: 8-row group stride; +4 staggers groups across banks
#define GST 36              // dense-graph row stride (floats), bank-staggered

// Scratch (allocation-free rule: __device__ globals)
__device__ float g_agg[(size_t)NSAMP * NN * HH];   // 15.7 MB
__device__ float g_mu [(size_t)NSAMP * NN * FF];   // 0.98 MB

// ---- packed f32x2 helpers (sm_103a) ---------------------------------------
#define FFMA2(acc, a, b) \
    asm("fma.rn.f32x2 %0, %1, %2, %0;" : "+l"(acc) : "l"(a), "l"(b))
#define MUL2(d, a, b) \
    asm("mul.rn.f32x2 %0, %1, %2;" : "=l"(d) : "l"(a), "l"(b))
#define PACKDUP(d, x) \
    asm("mov.b64 %0, {%1, %1};" : "=l"(d) : "r"(__float_as_uint(x)))
#define UNPACK2(x, y, p) \
    asm("mov.b64 {%0, %1}, %2;" : "=f"(x), "=f"(y) : "l"(p))
// acc += gdup * relu(apair + bpair)
#define AGG_STEP(acc, apair, bpair, gdup) \
    asm("{\n\t.reg .b32 lo, hi;\n\t.reg .b64 t;\n\t" \
        "add.rn.f32x2 t, %1, %2;\n\t" \
        "mov.b64 {lo, hi}, t;\n\t" \
        "max.f32 lo, lo, 0f00000000;\n\t" \
        "max.f32 hi, hi, 0f00000000;\n\t" \
        "mov.b64 t, {lo, hi};\n\t" \
        "fma.rn.f32x2 %0, %3, t, %0;\n\t}" \
        : "+l"(acc) : "l"(apair), "l"(bpair), "l"(gdup))

// PDL intrinsics (sm_90+)
#define GRID_DEP_SYNC()  cudaGridDependencySynchronize()
#define GRID_TRIGGER()   cudaTriggerProgrammaticLaunchCompletion()

// ---------------------------------------------------------------------------
// Edge kernel: 2 samples per CTA, 128 threads (all active). (R11 body + PDL)
// Trigger fires right after the last cross-kernel read (sx load).
// ---------------------------------------------------------------------------
struct EdgeSmem {
    float sW2[64*64];           // 16 KB
    float sW1[8*64];            //  2 KB
    float sB[8*GS];             // 17.5 KB : 64 rows in 8 groups ; becomes H
    float sgm[32][GST];         //  4.5 KB dense graph, zero diag + pad rows
    float sx[2][128];           //  1 KB (tail zeroed)
    float scnt[64];             // flat gr = smp*32 + row
    float sb1[64];
    float sb2[64];
};

__global__ __launch_bounds__(128, 5) void edge_kernel(
    const float* __restrict__ data, int mode,
    const float* __restrict__ graph,
    const float* __restrict__ W1, const float* __restrict__ b1,
    const float* __restrict__ W2, const float* __restrict__ b2)
{
    extern __shared__ char smem_raw[];
    EdgeSmem& S = *reinterpret_cast<EdgeSmem*>(smem_raw);

    const int tid = threadIdx.x;
    const int p   = blockIdx.x;
    const int bs  = p >> 5;
    const int c0  = p & 31;

    // ---- dependency-free prologue: weights, biases, graph, padding ----
    {
        const float4* w2v = reinterpret_cast<const float4*>(W2);
        float4* d2 = reinterpret_cast<float4*>(S.sW2);
        #pragma unroll
        for (int i = tid; i < 1024; i += 128) d2[i] = w2v[i];
        const float4* w1v = reinterpret_cast<const float4*>(W1);
        float4* d1 = reinterpret_cast<float4*>(S.sW1);
        d1[tid] = w1v[tid];
    }
    if (tid < 64) { S.sb1[tid] = b1[tid]; S.sb2[tid] = b2[tid]; }
    for (int e = tid; e < 900; e += 128) {
        int i = e / 30, j = e - i*30;
        S.sgm[i][j] = (i == j) ? 0.f
                      : graph[(size_t)bs*870 + i*29 + j - (j > i)];
    }
    if (tid < 30) { S.sgm[tid][30] = 0.f; S.sgm[tid][31] = 0.f; }
    if (tid < 64) S.sgm[30 + (tid >> 5)][tid & 31] = 0.f;      // pad g rows
    if (tid < 68) {                                            // zero pad rows
        S.sB[3*GS + 6*AST + tid] = 0.f;   // gr 30
        S.sB[3*GS + 7*AST + tid] = 0.f;   // gr 31
        S.sB[7*GS + 6*AST + tid] = 0.f;   // gr 62
        S.sB[7*GS + 7*AST + tid] = 0.f;   // gr 63
    }
    if (tid < 16) S.sx[tid >> 3][120 + (tid & 7)] = 0.f;       // pad x tail
    if (tid < 4)  S.scnt[((tid >> 1) << 5) + 30 + (tid & 1)] = 0.f;

    // ---- dependent read (g_mu in mode 1) happens only after prior grid done
    GRID_DEP_SYNC();
    for (int v = tid; v < 240; v += 128) {
        int h = v >= 120, idx = v - 120*h;
        int cc = c0 + 32*h, ss = bs*64 + cc;
        S.sx[h][idx] = (mode == 0)
            ? data[((size_t)bs*128 + 2*cc)*120 + idx]
            : g_mu[(size_t)ss*120 + idx];
    }
    __syncthreads();
    GRID_TRIGGER();             // last cross-kernel read done -> release dependent

    // ---- Stage A mapping: smp, rows r0..r0+3 (same sample), cols og..og+7
    const int smp = tid >> 6;
    const int rg  = (tid >> 3) & 7;
    const int cg  = tid & 7;
    const int r0  = rg * 4;
    const int og  = cg * 8;

    ull aA[4][4];               // A-projection, registers
    // ---- projections: A (registers) + B (smem) ----
    {
        float xr[4][4];
        #pragma unroll
        for (int rr = 0; rr < 4; rr++) {
            float4 xv = *reinterpret_cast<const float4*>(&S.sx[smp][(r0+rr)*4]);
            xr[rr][0]=xv.x; xr[rr][1]=xv.y; xr[rr][2]=xv.z; xr[rr][3]=xv.w;
        }
        ull aB[4][4];
        {
            ulonglong2 bq0 = *reinterpret_cast<const ulonglong2*>(&S.sb1[og]);
            ulonglong2 bq1 = *reinterpret_cast<const ulonglong2*>(&S.sb1[og+4]);
            ull bp[4] = {bq0.x, bq0.y, bq1.x, bq1.y};
            #pragma unroll
            for (int rr = 0; rr < 4; rr++)
                #pragma unroll
                for (int q = 0; q < 4; q++) { aA[rr][q] = bp[q]; aB[rr][q] = 0ULL; }
        }
        #pragma unroll
        for (int f = 0; f < 4; f++) {
            ulonglong2 wa0 = *reinterpret_cast<const ulonglong2*>(&S.sW1[f*64+og]);
            ulonglong2 wa1 = *reinterpret_cast<const ulonglong2*>(&S.sW1[f*64+og+4]);
            ulonglong2 wb0 = *reinterpret_cast<const ulonglong2*>(&S.sW1[(f+4)*64+og]);
            ulonglong2 wb1 = *reinterpret_cast<const ulonglong2*>(&S.sW1[(f+4)*64+og+4]);
            ull wa[4] = {wa0.x, wa0.y, wa1.x, wa1.y};
            ull wb[4] = {wb0.x, wb0.y, wb1.x, wb1.y};
            #pragma unroll
            for (int rr = 0; rr < 4; rr++) {
                ull xd; PACKDUP(xd, xr[rr][f]);
                #pragma unroll
                for (int q = 0; q < 4; q++) {
                    FFMA2(aA[rr][q], xd, wa[q]);
                    FFMA2(aB[rr][q], xd, wb[q]);
                }
            }
        }
        #pragma unroll
        for (int rr = 0; rr < 4; rr++) {
            int lr = r0 + rr;
            if (lr < 30) {
                float* dst = S.sB + (smp*4 + (lr>>3))*GS + (lr&7)*AST + og;
                ulonglong2 s0; s0.x = aB[rr][0]; s0.y = aB[rr][1];
                ulonglong2 s1; s1.x = aB[rr][2]; s1.y = aB[rr][3];
                *reinterpret_cast<ulonglong2*>(dst)   = s0;
                *reinterpret_cast<ulonglong2*>(dst+4) = s1;
            }
        }
    }
    __syncthreads();

    // ---- masked-ReLU aggregation: B[j] load serves 4 rows ----
    ull acc[4][4];
    float cnt[4] = {0.f, 0.f, 0.f, 0.f};
    {
        #pragma unroll
        for (int rr = 0; rr < 4; rr++)
            #pragma unroll
            for (int q = 0; q < 4; q++) acc[rr][q] = 0ULL;

        #pragma unroll
        for (int jg = 0; jg < 4; jg++) {
            const float* bg = S.sB + (smp*4 + jg)*GS + og;
            #pragma unroll
            for (int jh = 0; jh < 2; jh++) {
                const int j4 = jg*8 + jh*4;
                float ga[4][4];
                #pragma unroll
                for (int rr = 0; rr < 4; rr++) {
                    float4 gv = *reinterpret_cast<const float4*>(&S.sgm[r0+rr][j4]);
                    ga[rr][0]=gv.x; ga[rr][1]=gv.y; ga[rr][2]=gv.z; ga[rr][3]=gv.w;
                    cnt[rr] += gv.x + gv.y + gv.z + gv.w;
                }
                #pragma unroll
                for (int jj = 0; jj < 4; jj++) {
                    const float* bj = bg + (jh*4 + jj)*AST;
                    ulonglong2 b0 = *reinterpret_cast<const ulonglong2*>(bj);
                    ulonglong2 b1v = *reinterpret_cast<const ulonglong2*>(bj+4);
                    ull bv[4] = {b0.x, b0.y, b1v.x, b1v.y};
                    #pragma unroll
                    for (int rr = 0; rr < 4; rr++) {
                        ull gd; PACKDUP(gd, ga[rr][jj]);
                        #pragma unroll
                        for (int q = 0; q < 4; q++)
                            AGG_STEP(acc[rr][q], aA[rr][q], bv[q], gd);
                    }
                }
            }
        }
    }
    __syncthreads();            // all sB reads complete
    {
        #pragma unroll
        for (int rr = 0; rr < 4; rr++) {
            int lr = r0 + rr;
            if (lr < 30) {
                float* dst = S.sB + (smp*4 + (lr>>3))*GS + (lr&7)*AST + og;
                ulonglong2 s0; s0.x = acc[rr][0]; s0.y = acc[rr][1];
                ulonglong2 s1; s1.x = acc[rr][2]; s1.y = acc[rr][3];
                *reinterpret_cast<ulonglong2*>(dst)   = s0;
                *reinterpret_cast<ulonglong2*>(dst+4) = s1;
            }
        }
        if (cg == 0) {
            #pragma unroll
            for (int rr = 0; rr < 4; rr++)
                if (r0 + rr < 30) S.scnt[smp*32 + r0 + rr] = cnt[rr];
        }
    }
    __syncthreads();

    // ---- Stage B: agg = H @ W2 + cnt*b2. 8 rows x 4 cols per thread. ----
    {
        const int rg2 = tid >> 4;          // 0..7 : group rg2 = rows rg2*8..+7
        const int oc  = (tid & 15) * 4;    // 0..60
        const float* hb = S.sB + rg2*GS;
        ull acc2[8][2];
        {
            ulonglong2 b2p = *reinterpret_cast<const ulonglong2*>(&S.sb2[oc]);
            #pragma unroll
            for (int r = 0; r < 8; r++) {
                ull cd; PACKDUP(cd, S.scnt[rg2*8 + r]);
                MUL2(acc2[r][0], cd, b2p.x);
                MUL2(acc2[r][1], cd, b2p.y);
            }
        }
        #pragma unroll 2
        for (int k4 = 0; k4 < 64; k4 += 4) {
            ulonglong2 w[4];
            #pragma unroll
            for (int kk = 0; kk < 4; kk++)
                w[kk] = *reinterpret_cast<const ulonglong2*>(&S.sW2[(k4+kk)*64 + oc]);
            float4 hv[8];
            #pragma unroll
            for (int r = 0; r < 8; r++)
                hv[r] = *reinterpret_cast<const float4*>(hb + r*AST + k4);
            float ha[8][4];
            #pragma unroll
            for (int r = 0; r < 8; r++) {
                ha[r][0]=hv[r].x; ha[r][1]=hv[r].y; ha[r][2]=hv[r].z; ha[r][3]=hv[r].w;
            }
            #pragma unroll
            for (int kk = 0; kk < 4; kk++) {
                #pragma unroll
                for (int r = 0; r < 8; r++) {
                    ull hd; PACKDUP(hd, ha[r][kk]);
                    FFMA2(acc2[r][0], hd, w[kk].x);
                    FFMA2(acc2[r][1], hd, w[kk].y);
                }
            }
        }
        const int sb0 = bs*64 + c0;
        #pragma unroll
        for (int r = 0; r < 8; r++) {
            int gr = rg2*8 + r;
            int sm2 = gr >> 5, row = gr & 31;
            if (row < 30) {
                size_t base = ((size_t)(sb0 + 32*sm2)*NN + row)*HH + oc;
                ulonglong2 st; st.x = acc2[r][0]; st.y = acc2[r][1];
                *reinterpret_cast<ulonglong2*>(&g_agg[base]) = st;
            }
        }
    }
}

// ---------------------------------------------------------------------------
// Node MLP kernel: 64 ->relu-> 64 ->relu-> 64 -> 4. 4 samples/CTA, 128 thr.
// R11 champion body + PDL; trigger fires right after the g_agg->smem load.
// ---------------------------------------------------------------------------
struct NodeSmem {
    float sW[64*64];            // 16 KB, W1 then W2
    float sW3[64*4];
    float buf[15*GS];           // 32.1 KB : 120 rows in 15 groups of 8
    float sb1[64];
    float sb2[64];
    float sb3[8];
};

__device__ __forceinline__ void gemm8_compute(
    const float* __restrict__ r0,      // &buf[ig*GS]
    const float* __restrict__ sW, const float* __restrict__ sb,
    int og, ull acc[8][4])
{
    {
        ulonglong2 bq0 = *reinterpret_cast<const ulonglong2*>(&sb[og]);
        ulonglong2 bq1 = *reinterpret_cast<const ulonglong2*>(&sb[og+4]);
        ull bp[4] = {bq0.x, bq0.y, bq1.x, bq1.y};
        #pragma unroll
        for (int r = 0; r < 8; r++)
            #pragma unroll
            for (int q = 0; q < 4; q++) acc[r][q] = bp[q];
    }
    #pragma unroll 2
    for (int k4 = 0; k4 < 64; k4 += 4) {
        float4 hv[8];
        #pragma unroll
        for (int r = 0; r < 8; r++)
            hv[r] = *reinterpret_cast<const float4*>(r0 + r*AST + k4);
        float ha[8][4];
        #pragma unroll
        for (int r = 0; r < 8; r++) {
            ha[r][0]=hv[r].x; ha[r][1]=hv[r].y; ha[r][2]=hv[r].z; ha[r][3]=hv[r].w;
        }
        #pragma unroll
        for (int kk = 0; kk < 4; kk++) {
            ulonglong2 w0 = *reinterpret_cast<const ulonglong2*>(&sW[(k4+kk)*64+og]);
            ulonglong2 w1 = *reinterpret_cast<const ulonglong2*>(&sW[(k4+kk)*64+og+4]);
            ull wv[4] = {w0.x, w0.y, w1.x, w1.y};
            #pragma unroll
            for (int r = 0; r < 8; r++) {
                ull hd; PACKDUP(hd, ha[r][kk]);
                #pragma unroll
                for (int q = 0; q < 4; q++) FFMA2(acc[r][q], hd, wv[q]);
            }
        }
    }
}

__device__ __forceinline__ void gemm8_store_relu(
    float* __restrict__ w0, ull acc[8][4])   // w0 = &buf[ig*GS + og]
{
    #pragma unroll
    for (int r = 0; r < 8; r++) {
        float* dst = w0 + r*AST;
        float x0,x1,x2,x3,x4,x5,x6,x7;
        UNPACK2(x0,x1,acc[r][0]); UNPACK2(x2,x3,acc[r][1]);
        UNPACK2(x4,x5,acc[r][2]); UNPACK2(x6,x7,acc[r][3]);
        *reinterpret_cast<float4*>(dst) =
            make_float4(fmaxf(x0,0.f),fmaxf(x1,0.f),fmaxf(x2,0.f),fmaxf(x3,0.f));
        *reinterpret_cast<float4*>(dst+4) =
            make_float4(fmaxf(x4,0.f),fmaxf(x5,0.f),fmaxf(x6,0.f),fmaxf(x7,0.f));
    }
}

__global__ __launch_bounds__(128, 3) void node_kernel(
    const float* __restrict__ mW1, const float* __restrict__ mb1,
    const float* __restrict__ mW2, const float* __restrict__ mb2,
    const float* __restrict__ mW3, const float* __restrict__ mb3,
    const float* __restrict__ vW1, const float* __restrict__ vb1,
    const float* __restrict__ vW2, const float* __restrict__ vb2,
    const float* __restrict__ vW3, const float* __restrict__ vb3,
    float* __restrict__ out, int t)
{
    extern __shared__ char smem_raw[];
    NodeSmem& S = *reinterpret_cast<NodeSmem*>(smem_raw);

    const int tid = threadIdx.x;
    const int p   = blockIdx.x;       // 0..511
    const int is_var = blockIdx.y;
    const int bs  = p >> 4;           // 0..31
    const int c0  = p & 15;           // samples c0 + 16*smp

    const float* W1 = is_var ? vW1 : mW1;
    const float* W2 = is_var ? vW2 : mW2;
    const float* W3 = is_var ? vW3 : mW3;
    const float* b1 = is_var ? vb1 : mb1;
    const float* b2 = is_var ? vb2 : mb2;
    const float* b3 = is_var ? vb3 : mb3;

    // ---- dependency-free prologue: W1 + W3 + biases ----
    {
        const float4* w1v = reinterpret_cast<const float4*>(W1);
        float4* s1 = reinterpret_cast<float4*>(S.sW);
        #pragma unroll
        for (int i = tid; i < 1024; i += 128) s1[i] = w1v[i];
        S.sW3[tid] = W3[tid]; S.sW3[tid+128] = W3[tid+128];
    }
    if (tid < 64) { S.sb1[tid] = b1[tid]; S.sb2[tid] = b2[tid]; }
    if (tid < 4)  S.sb3[tid] = b3[tid];
    if (tid >= 4 && tid < 8) S.sb3[tid] = 0.f;

    // ---- dependent read: g_agg written by edge kernel ----
    GRID_DEP_SYNC();
    {
        const float4* ab = reinterpret_cast<const float4*>(g_agg);
        #pragma unroll
        for (int v = tid; v < 1920; v += 128) {
            int smp = v / 480, vv = v - smp*480;
            int row = vv >> 4, cp = vv & 15;
            int inst = smp*30 + row;
            float4 val = ab[(size_t)(bs*64 + c0 + 16*smp)*480 + vv];
            *reinterpret_cast<float4*>(&S.buf[(inst>>3)*GS + (inst&7)*AST + cp*4]) = val;
        }
    }
    __syncthreads();
    GRID_TRIGGER();             // last cross-kernel read done -> release dependent

    const int ig = tid >> 3, cg = tid & 7;
    const int og = cg*8;
    const float* r0 = &S.buf[ig*GS];
    float*       w0 = &S.buf[ig*GS + og];

    ull acc[8][4];
    // Layer 1 (sW = W1)
    if (tid < 120) gemm8_compute(r0, S.sW, S.sb1, og, acc);
    __syncthreads();
    if (tid < 120) gemm8_store_relu(w0, acc);
    {
        const float4* w2v = reinterpret_cast<const float4*>(W2);
        float4* s1 = reinterpret_cast<float4*>(S.sW);
        #pragma unroll
        for (int i = tid; i < 1024; i += 128) s1[i] = w2v[i];
    }
    __syncthreads();
    // Layer 2 (sW = W2)
    if (tid < 120) gemm8_compute(r0, S.sW, S.sb2, og, acc);
    __syncthreads();
    if (tid < 120) gemm8_store_relu(w0, acc);
    __syncthreads();

    // Layer 3: 64 -> 4. 120 threads, one instance each.
    if (tid < 120) {
        const int smp = tid / 30, n = tid - smp*30;
        const float* hr = &S.buf[(tid>>3)*GS + (tid&7)*AST];
        ulonglong2 b3q = *reinterpret_cast<const ulonglong2*>(&S.sb3[0]);
        ull a01 = b3q.x, a23 = b3q.y;
        #pragma unroll 4
        for (int k4 = 0; k4 < 64; k4 += 4) {
            float4 hv = *reinterpret_cast<const float4*>(hr + k4);
            float ha[4] = {hv.x, hv.y, hv.z, hv.w};
            #pragma unroll
            for (int kk = 0; kk < 4; kk++) {
                ulonglong2 w = *reinterpret_cast<const ulonglong2*>(&S.sW3[(k4+kk)*4]);
                ull hd; PACKDUP(hd, ha[kk]);
                FFMA2(a01, hd, w.x);
                FFMA2(a23, hd, w.y);
            }
        }
        float v0,v1,v2,v3;
        UNPACK2(v0,v1,a01); UNPACK2(v2,v3,a23);
        float v[4] = {v0,v1,v2,v3};
        if (is_var) {
            #pragma unroll
            for (int q = 0; q < 4; q++) {
                float x = v[q];
                float sp = (x > 20.f) ? x : log1pf(expf(x));
                v[q] = fminf(fmaxf(sp, 1e-8f), 100.f);
            }
        }
        const int c = c0 + 16*smp;
        const int s = bs*64 + c;
        if (!is_var && t == 0)
            *reinterpret_cast<float4*>(&g_mu[(size_t)s*120 + n*4]) =
                make_float4(v[0],v[1],v[2],v[3]);
        const int kt = 2*c + t;
        if (kt < TOUT) {
            size_t o = (((size_t)bs*TOUT + kt)*NN + n)*FF;
            *reinterpret_cast<float4*>(&out[o + (is_var ? (size_t)VAROFF : 0)]) =
                make_float4(v[0],v[1],v[2],v[3]);
        }
    }
}

// ---------------------------------------------------------------------------
extern "C" void kernel_launch(void* const* d_in, const int* in_sizes, int n_in,
                              void* d_out, int out_size) {
    const float* data    = (const float*)d_in[0];
    const float* graph   = (const float*)d_in[1];
    const float* msg_W1  = (const float*)d_in[2];
    const float* msg_b1  = (const float*)d_in[3];
    const float* msg_W2  = (const float*)d_in[4];
    const float* msg_b2  = (const float*)d_in[5];
    const float* mean_W1 = (const float*)d_in[6];
    const float* mean_b1 = (const float*)d_in[7];
    const float* mean_W2 = (const float*)d_in[8];
    const float* mean_b2 = (const float*)d_in[9];
    const float* mean_W3 = (const float*)d_in[10];
    const float* mean_b3 = (const float*)d_in[11];
    const float* var_W1  = (const float*)d_in[12];
    const float* var_b1  = (const float*)d_in[13];
    const float* var_W2  = (const float*)d_in[14];
    const float* var_b2  = (const float*)d_in[15];
    const float* var_W3  = (const float*)d_in[16];
    const float* var_b3  = (const float*)d_in[17];
    float* out = (float*)d_out;

    cudaFuncSetAttribute(edge_kernel, cudaFuncAttributeMaxDynamicSharedMemorySize,
                         (int)sizeof(EdgeSmem));
    cudaFuncSetAttribute(node_kernel, cudaFuncAttributeMaxDynamicSharedMemorySize,
                         (int)sizeof(NodeSmem));

    // PDL launch configs: programmatic stream serialization on every launch
    cudaLaunchAttribute attrs[1];
    attrs[0].id = cudaLaunchAttributeProgrammaticStreamSerialization;
    attrs[0].val.programmaticStreamSerializationAllowed = 1;

    cudaLaunchConfig_t ecfg = {};
    ecfg.gridDim  = dim3(NSAMP/2, 1, 1);
    ecfg.blockDim = dim3(128, 1, 1);
    ecfg.dynamicSmemBytes = sizeof(EdgeSmem);
    ecfg.stream = 0;
    ecfg.attrs = attrs; ecfg.numAttrs = 1;

    cudaLaunchConfig_t ncfg = {};
    ncfg.gridDim  = dim3(NSAMP/4, 2, 1);
    ncfg.blockDim = dim3(128, 1, 1);
    ncfg.dynamicSmemBytes = sizeof(NodeSmem);
    ncfg.stream = 0;
    ncfg.attrs = attrs; ncfg.numAttrs = 1;

    for (int t = 0; t < 2; t++) {
        cudaLaunchKernelEx(&ecfg, edge_kernel, data, t, graph,
                           msg_W1, msg_b1, msg_W2, msg_b2);
        cudaLaunchKernelEx(&ncfg, node_kernel,
                           mean_W1, mean_b1, mean_W2, mean_b2, mean_W3, mean_b3,
                           var_W1,  var_b1,  var_W2,  var_b2,  var_W3,  var_b3,
                           out, t);
    }
}